// round 6
// baseline (speedup 1.0000x reference)
#include <cuda_runtime.h>
#include <cuda_fp16.h>
#include <math.h>
#include <stdint.h>

// Problem constants
#define T_TOK 512
#define H_DIM 2048
#define E_NUM 64
#define TOPK  8
#define I_DIM 768

// ---------------- scratch ----------------
__device__ float g_act[T_TOK * TOPK * I_DIM];
__device__ float g_partial[(size_t)T_TOK * TOPK * H_DIM];
__device__ float g_sact[T_TOK * I_DIM];
__device__ int   g_counts[E_NUM];
__device__ int   g_offsets[E_NUM + 1];
__device__ int   g_cursor[E_NUM];
__device__ int   g_tki[T_TOK * TOPK];
__device__ float g_tkw[T_TOK * TOPK];
__device__ int   g_tok[T_TOK * TOPK];
__device__ int   g_dest[T_TOK * TOPK];
__device__ float g_slotw[T_TOK * TOPK];

// ---------------- router ----------------
__global__ void router_kernel(const float* __restrict__ x,
                              const float* __restrict__ gate_w,
                              const float* __restrict__ gate_b) {
    int t = blockIdx.x;
    __shared__ float sx[H_DIM];
    __shared__ float sscore[E_NUM];
    __shared__ float sbias[E_NUM];
    int tid = threadIdx.x;  // 0..63

    const float4* xr = (const float4*)(x + (size_t)t * H_DIM);
    float4* sx4 = (float4*)sx;
    for (int i = tid; i < H_DIM / 4; i += 64) sx4[i] = xr[i];
    __syncthreads();

    const float* w = gate_w + (size_t)tid * H_DIM;
    float acc = 0.f;
    #pragma unroll 4
    for (int h = 0; h < H_DIM; h += 4) {
        float4 wv = *(const float4*)(w + h);
        acc += wv.x * sx[h] + wv.y * sx[h + 1] + wv.z * sx[h + 2] + wv.w * sx[h + 3];
    }
    float score = 1.f / (1.f + expf(-acc));
    sscore[tid] = score;
    sbias[tid]  = score + gate_b[tid];
    __syncthreads();

    if (tid == 0) {
        int   idx[TOPK];
        float wts[TOPK];
        float sum = 0.f;
        for (int k = 0; k < TOPK; k++) {
            float best = -1e30f; int bi = 0;
            for (int e = 0; e < E_NUM; e++) {
                float v = sbias[e];
                if (v > best) { best = v; bi = e; }
            }
            sbias[bi] = -1e30f;
            idx[k] = bi;
            wts[k] = sscore[bi];
            sum += wts[k];
        }
        float inv = 1.f / (sum + 1e-20f);
        for (int k = 0; k < TOPK; k++) {
            g_tki[t * TOPK + k] = idx[k];
            g_tkw[t * TOPK + k] = wts[k] * inv;
            atomicAdd(&g_counts[idx[k]], 1);
        }
    }
}

__global__ void zero_counts_kernel() { g_counts[threadIdx.x] = 0; }

__global__ void offsets_kernel() {
    int o = 0;
    for (int e = 0; e < E_NUM; e++) {
        g_offsets[e] = o;
        o += g_counts[e];
        g_cursor[e] = 0;
    }
    g_offsets[E_NUM] = o;
}

__global__ void scatter_kernel() {
    int i = blockIdx.x * blockDim.x + threadIdx.x;
    if (i >= T_TOK * TOPK) return;
    int e = g_tki[i];
    int pos = g_offsets[e] + atomicAdd(&g_cursor[e], 1);
    g_tok[pos]   = i / TOPK;
    g_dest[pos]  = i;
    g_slotw[pos] = g_tkw[i];
}

// ---------------- tensor-core helpers ----------------
__device__ __forceinline__ uint32_t smem_u32(const void* p) {
    return (uint32_t)__cvta_generic_to_shared(p);
}
__device__ __forceinline__ void ldsm4(uint32_t* r, uint32_t addr) {
    asm volatile("ldmatrix.sync.aligned.m8n8.x4.shared.b16 {%0,%1,%2,%3}, [%4];"
                 : "=r"(r[0]), "=r"(r[1]), "=r"(r[2]), "=r"(r[3]) : "r"(addr));
}
__device__ __forceinline__ void ldsm2t(uint32_t* r, uint32_t addr) {
    asm volatile("ldmatrix.sync.aligned.m8n8.x2.trans.shared.b16 {%0,%1}, [%2];"
                 : "=r"(r[0]), "=r"(r[1]) : "r"(addr));
}
__device__ __forceinline__ void mma16816(float* c, const uint32_t* a, const uint32_t* b) {
    asm volatile(
        "mma.sync.aligned.m16n8k16.row.col.f32.f16.f16.f32 "
        "{%0,%1,%2,%3}, {%4,%5,%6,%7}, {%8,%9}, {%0,%1,%2,%3};"
        : "+f"(c[0]), "+f"(c[1]), "+f"(c[2]), "+f"(c[3])
        : "r"(a[0]), "r"(a[1]), "r"(a[2]), "r"(a[3]), "r"(b[0]), "r"(b[1]));
}

// split-fp16: 8 floats -> hi + lo halves
__device__ __forceinline__ void cvt8_hilo(const float4& va, const float4& vb,
                                          __half* hrow, __half* lrow) {
    float f[8] = {va.x, va.y, va.z, va.w, vb.x, vb.y, vb.z, vb.w};
    #pragma unroll
    for (int j = 0; j < 8; j += 2) {
        __half h0 = __float2half(f[j]);
        __half h1 = __float2half(f[j + 1]);
        __half l0 = __float2half(f[j]     - __half2float(h0));
        __half l1 = __float2half(f[j + 1] - __half2float(h1));
        *(__half2*)(hrow + j) = __halves2half2(h0, h1);
        *(__half2*)(lrow + j) = __halves2half2(l0, l1);
    }
}
// plain fp16: 8 floats -> hi only
__device__ __forceinline__ void cvt8_hi(const float4& va, const float4& vb, __half* hrow) {
    float f[8] = {va.x, va.y, va.z, va.w, vb.x, vb.y, vb.z, vb.w};
    #pragma unroll
    for (int j = 0; j < 8; j += 2)
        *(__half2*)(hrow + j) = __halves2half2(__float2half(f[j]), __float2half(f[j + 1]));
}

#define ASTRIDE 40  // halfs per A smem row (80B stride, conflict-free over 8 rows)
#define BSTRIDE 72  // halfs per B smem row (144B stride, conflict-free over 8 rows)

// ---------------- grouped dual-B GEMM + fused SiLU ----------------
// fp16 split-A x fp16 B. BM=128, BN=64, BK=32.
// 256 threads = 8 warps (4M x 2N), warp tile 32x32.
// BM=128 so each expert usually needs ONE m-tile -> weights stream exactly once.
template <bool SHARED>
__global__ void __launch_bounds__(256) gateup_kernel(
    const float* __restrict__ x,
    const float* __restrict__ w_gate_all,
    const float* __restrict__ w_up_all) {

    const int e = SHARED ? 0 : blockIdx.z;
    int base, nrows;
    if (SHARED) { base = 0; nrows = T_TOK; }
    else        { base = g_offsets[e]; nrows = g_offsets[e + 1] - base; }

    const int m0 = blockIdx.y * 128;
    if (m0 >= nrows) return;
    const int n0 = blockIdx.x * 64;

    const float* wg = SHARED ? w_gate_all : (w_gate_all + (size_t)e * H_DIM * I_DIM);
    const float* wu = SHARED ? w_up_all   : (w_up_all   + (size_t)e * H_DIM * I_DIM);

    __shared__ __align__(16) __half Ah[128][ASTRIDE];
    __shared__ __align__(16) __half Al[128][ASTRIDE];
    __shared__ __align__(16) __half Bg[32][BSTRIDE];
    __shared__ __align__(16) __half Bu[32][BSTRIDE];

    const int tid = threadIdx.x;
    // A loader: row = tid/2 (128 rows), k-offset (tid%2)*16 -> 16 floats
    const int ar  = tid >> 1;
    const int akb = (tid & 1) * 16;
    const bool avalid = (m0 + ar < nrows);
    int tokid = 0;
    if (avalid) tokid = SHARED ? (m0 + ar) : g_tok[base + m0 + ar];
    const float* aptr = x + (size_t)tokid * H_DIM + akb;
    // B loader: k-row = tid/8 (32 rows), n-offset (tid%8)*8 -> 8 floats per matrix
    const int bk = tid >> 3;
    const int bn = (tid & 7) * 8;
    const float* gptr = wg + (size_t)bk * I_DIM + n0 + bn;
    const float* uptr = wu + (size_t)bk * I_DIM + n0 + bn;

    const int wid  = tid >> 5;
    const int lane = tid & 31;
    const int wm = wid >> 1;   // 0..3 (rows, 32 each)
    const int wn = wid & 1;    // 0..1 (cols, 32 each)
    const int g  = lane >> 2;
    const int tg = lane & 3;

    float cg[2][4][4] = {};
    float cu[2][4][4] = {};

    const float4 z4 = make_float4(0.f, 0.f, 0.f, 0.f);
    float4 pa[4], pg[2], pu[2];
    #pragma unroll
    for (int j = 0; j < 4; j++)
        pa[j] = avalid ? *(const float4*)(aptr + j * 4) : z4;
    pg[0] = *(const float4*)(gptr);
    pg[1] = *(const float4*)(gptr + 4);
    pu[0] = *(const float4*)(uptr);
    pu[1] = *(const float4*)(uptr + 4);

    for (int k0 = 0; k0 < H_DIM; k0 += 32) {
        cvt8_hilo(pa[0], pa[1], &Ah[ar][akb],     &Al[ar][akb]);
        cvt8_hilo(pa[2], pa[3], &Ah[ar][akb + 8], &Al[ar][akb + 8]);
        cvt8_hi(pg[0], pg[1], &Bg[bk][bn]);
        cvt8_hi(pu[0], pu[1], &Bu[bk][bn]);
        __syncthreads();

        if (k0 + 32 < H_DIM) {
            int kn = k0 + 32;
            const float* gp = gptr + (size_t)kn * I_DIM;
            const float* up = uptr + (size_t)kn * I_DIM;
            #pragma unroll
            for (int j = 0; j < 4; j++)
                pa[j] = avalid ? *(const float4*)(aptr + kn + j * 4) : z4;
            pg[0] = *(const float4*)(gp);
            pg[1] = *(const float4*)(gp + 4);
            pu[0] = *(const float4*)(up);
            pu[1] = *(const float4*)(up + 4);
        }

        #pragma unroll
        for (int ks = 0; ks < 32; ks += 16) {
            uint32_t ah_f[2][4], al_f[2][4];
            #pragma unroll
            for (int mi = 0; mi < 2; mi++) {
                int row = wm * 32 + mi * 16 + (lane & 15);
                int col = ks + ((lane & 16) >> 1);
                ldsm4(ah_f[mi], smem_u32(&Ah[row][col]));
                ldsm4(al_f[mi], smem_u32(&Al[row][col]));
            }
            uint32_t bg_f[4][2], bu_f[4][2];
            #pragma unroll
            for (int ni = 0; ni < 4; ni++) {
                int brow = ks + (lane & 15);
                int bcol = wn * 32 + ni * 8;
                ldsm2t(bg_f[ni], smem_u32(&Bg[brow][bcol]));
                ldsm2t(bu_f[ni], smem_u32(&Bu[brow][bcol]));
            }
            #pragma unroll
            for (int mi = 0; mi < 2; mi++) {
                #pragma unroll
                for (int ni = 0; ni < 4; ni++) {
                    mma16816(cg[mi][ni], ah_f[mi], bg_f[ni]);
                    mma16816(cg[mi][ni], al_f[mi], bg_f[ni]);
                    mma16816(cu[mi][ni], ah_f[mi], bu_f[ni]);
                    mma16816(cu[mi][ni], al_f[mi], bu_f[ni]);
                }
            }
        }
        __syncthreads();
    }

    // epilogue: silu(g)*u
    #pragma unroll
    for (int mi = 0; mi < 2; mi++) {
        int r0 = m0 + wm * 32 + mi * 16 + g;
        int r1 = r0 + 8;
        #pragma unroll
        for (int ni = 0; ni < 4; ni++) {
            int c0 = n0 + wn * 32 + ni * 8 + tg * 2;
            if (r0 < nrows) {
                float* orow = SHARED ? (g_sact + (size_t)r0 * I_DIM)
                                     : (g_act  + (size_t)(base + r0) * I_DIM);
                float g0 = cg[mi][ni][0], u0 = cu[mi][ni][0];
                float g1 = cg[mi][ni][1], u1 = cu[mi][ni][1];
                orow[c0]     = (g0 / (1.f + expf(-g0))) * u0;
                orow[c0 + 1] = (g1 / (1.f + expf(-g1))) * u1;
            }
            if (r1 < nrows) {
                float* orow = SHARED ? (g_sact + (size_t)r1 * I_DIM)
                                     : (g_act  + (size_t)(base + r1) * I_DIM);
                float g2 = cg[mi][ni][2], u2 = cu[mi][ni][2];
                float g3 = cg[mi][ni][3], u3 = cu[mi][ni][3];
                orow[c0]     = (g2 / (1.f + expf(-g2))) * u2;
                orow[c0 + 1] = (g3 / (1.f + expf(-g3))) * u3;
            }
        }
    }
}

// ---------------- grouped down-proj GEMM ----------------
// fp16 split-A x fp16 B. BM=128, BN=64, BK=32, 256 threads (4x2 warps, 32x32 tile).
template <bool SHARED>
__global__ void __launch_bounds__(256) down_kernel(
    const float* __restrict__ w_down_all,
    float* __restrict__ out) {

    const int e = SHARED ? 0 : blockIdx.z;
    int base, nrows;
    if (SHARED) { base = 0; nrows = T_TOK; }
    else        { base = g_offsets[e]; nrows = g_offsets[e + 1] - base; }

    const int m0 = blockIdx.y * 128;
    if (m0 >= nrows) return;
    const int n0 = blockIdx.x * 64;

    const float* wd = SHARED ? w_down_all : (w_down_all + (size_t)e * I_DIM * H_DIM);
    const float* Asrc = SHARED ? g_sact : g_act;

    __shared__ __align__(16) __half Ah[128][ASTRIDE];
    __shared__ __align__(16) __half Al[128][ASTRIDE];
    __shared__ __align__(16) __half Bh[32][BSTRIDE];

    const int tid = threadIdx.x;
    const int ar  = tid >> 1;
    const int akb = (tid & 1) * 16;
    const bool avalid = (m0 + ar < nrows);
    const float* aptr = Asrc + (size_t)(base + (avalid ? (m0 + ar) : 0)) * I_DIM + akb;

    const int bk = tid >> 3;
    const int bn = (tid & 7) * 8;
    const float* bptr = wd + (size_t)bk * H_DIM + n0 + bn;

    const int wid  = tid >> 5;
    const int lane = tid & 31;
    const int wm = wid >> 1;
    const int wn = wid & 1;
    const int g  = lane >> 2;
    const int tg = lane & 3;

    float acc[2][4][4] = {};

    const float4 z4 = make_float4(0.f, 0.f, 0.f, 0.f);
    float4 pa[4], pb[2];
    #pragma unroll
    for (int j = 0; j < 4; j++)
        pa[j] = avalid ? *(const float4*)(aptr + j * 4) : z4;
    pb[0] = *(const float4*)(bptr);
    pb[1] = *(const float4*)(bptr + 4);

    for (int k0 = 0; k0 < I_DIM; k0 += 32) {
        cvt8_hilo(pa[0], pa[1], &Ah[ar][akb],     &Al[ar][akb]);
        cvt8_hilo(pa[2], pa[3], &Ah[ar][akb + 8], &Al[ar][akb + 8]);
        cvt8_hi(pb[0], pb[1], &Bh[bk][bn]);
        __syncthreads();

        if (k0 + 32 < I_DIM) {
            int kn = k0 + 32;
            const float* bp = bptr + (size_t)kn * H_DIM;
            #pragma unroll
            for (int j = 0; j < 4; j++)
                pa[j] = avalid ? *(const float4*)(aptr + kn + j * 4) : z4;
            pb[0] = *(const float4*)(bp);
            pb[1] = *(const float4*)(bp + 4);
        }

        #pragma unroll
        for (int ks = 0; ks < 32; ks += 16) {
            uint32_t ah_f[2][4], al_f[2][4];
            #pragma unroll
            for (int mi = 0; mi < 2; mi++) {
                int row = wm * 32 + mi * 16 + (lane & 15);
                int col = ks + ((lane & 16) >> 1);
                ldsm4(ah_f[mi], smem_u32(&Ah[row][col]));
                ldsm4(al_f[mi], smem_u32(&Al[row][col]));
            }
            uint32_t b_f[4][2];
            #pragma unroll
            for (int ni = 0; ni < 4; ni++) {
                int brow = ks + (lane & 15);
                int bcol = wn * 32 + ni * 8;
                ldsm2t(b_f[ni], smem_u32(&Bh[brow][bcol]));
            }
            #pragma unroll
            for (int mi = 0; mi < 2; mi++) {
                #pragma unroll
                for (int ni = 0; ni < 4; ni++) {
                    mma16816(acc[mi][ni], ah_f[mi], b_f[ni]);
                    mma16816(acc[mi][ni], al_f[mi], b_f[ni]);
                }
            }
        }
        __syncthreads();
    }

    #pragma unroll
    for (int mi = 0; mi < 2; mi++) {
        int rr[2] = {m0 + wm * 32 + mi * 16 + g, m0 + wm * 32 + mi * 16 + g + 8};
        #pragma unroll
        for (int half = 0; half < 2; half++) {
            int r = rr[half];
            if (r >= nrows) continue;
            #pragma unroll
            for (int ni = 0; ni < 4; ni++) {
                int c0 = n0 + wn * 32 + ni * 8 + tg * 2;
                float v0 = acc[mi][ni][half * 2 + 0];
                float v1 = acc[mi][ni][half * 2 + 1];
                if (SHARED) {
                    float* orow = out + (size_t)r * H_DIM;
                    orow[c0]     = v0;
                    orow[c0 + 1] = v1;
                } else {
                    int slot = base + r;
                    int dest = g_dest[slot];
                    float w  = g_slotw[slot];
                    float* orow = g_partial + (size_t)dest * H_DIM;
                    orow[c0]     = w * v0;
                    orow[c0 + 1] = w * v1;
                }
            }
        }
    }
}

// ---------------- combine ----------------
__global__ void combine_kernel(float* __restrict__ out) {
    int i = blockIdx.x * blockDim.x + threadIdx.x;
    int t = i / H_DIM;
    int h = i - t * H_DIM;
    float acc = out[i];
    #pragma unroll
    for (int k = 0; k < TOPK; k++)
        acc += g_partial[((size_t)t * TOPK + k) * H_DIM + h];
    out[i] = acc;
}

// ---------------- launch ----------------
extern "C" void kernel_launch(void* const* d_in, const int* in_sizes, int n_in,
                              void* d_out, int out_size) {
    const float* x       = (const float*)d_in[0];
    const float* gate_w  = (const float*)d_in[1];
    const float* gate_b  = (const float*)d_in[2];
    const float* w_gate  = (const float*)d_in[3];
    const float* w_up    = (const float*)d_in[4];
    const float* w_down  = (const float*)d_in[5];
    const float* sw_gate = (const float*)d_in[6];
    const float* sw_up   = (const float*)d_in[7];
    const float* sw_down = (const float*)d_in[8];
    float* out = (float*)d_out;

    zero_counts_kernel<<<1, 64>>>();
    router_kernel<<<T_TOK, 64>>>(x, gate_w, gate_b);
    offsets_kernel<<<1, 1>>>();
    scatter_kernel<<<(T_TOK * TOPK + 255) / 256, 256>>>();

    // m-tiles of 128: worst case an expert gets all 512 tokens -> 4 tiles (early-out otherwise)
    gateup_kernel<false><<<dim3(I_DIM / 64, 4, E_NUM), 256>>>(x, w_gate, w_up);
    gateup_kernel<true><<<dim3(I_DIM / 64, T_TOK / 128, 1), 256>>>(x, sw_gate, sw_up);
    down_kernel<false><<<dim3(H_DIM / 64, 4, E_NUM), 256>>>(w_down, nullptr);
    down_kernel<true><<<dim3(H_DIM / 64, T_TOK / 128, 1), 256>>>(sw_down, out);
    combine_kernel<<<(T_TOK * H_DIM) / 256, 256>>>(out);
}

// round 7
// speedup vs baseline: 1.1023x; 1.1023x over previous
#include <cuda_runtime.h>
#include <cuda_fp16.h>
#include <math.h>
#include <stdint.h>

// Problem constants
#define T_TOK 512
#define H_DIM 2048
#define E_NUM 64
#define TOPK  8
#define I_DIM 768

// ---------------- scratch ----------------
__device__ float g_act[T_TOK * TOPK * I_DIM];
__device__ float g_partial[(size_t)T_TOK * TOPK * H_DIM];
__device__ float g_sact[T_TOK * I_DIM];
__device__ int   g_counts[E_NUM];
__device__ int   g_offsets[E_NUM + 1];
__device__ int   g_cursor[E_NUM];
__device__ int   g_tki[T_TOK * TOPK];
__device__ float g_tkw[T_TOK * TOPK];
__device__ int   g_tok[T_TOK * TOPK];
__device__ int   g_dest[T_TOK * TOPK];
__device__ float g_slotw[T_TOK * TOPK];

// ---------------- router ----------------
__global__ void router_kernel(const float* __restrict__ x,
                              const float* __restrict__ gate_w,
                              const float* __restrict__ gate_b) {
    int t = blockIdx.x;
    __shared__ float sx[H_DIM];
    __shared__ float sscore[E_NUM];
    __shared__ float sbias[E_NUM];
    int tid = threadIdx.x;  // 0..63

    const float4* xr = (const float4*)(x + (size_t)t * H_DIM);
    float4* sx4 = (float4*)sx;
    for (int i = tid; i < H_DIM / 4; i += 64) sx4[i] = xr[i];
    __syncthreads();

    const float* w = gate_w + (size_t)tid * H_DIM;
    float acc = 0.f;
    #pragma unroll 4
    for (int h = 0; h < H_DIM; h += 4) {
        float4 wv = *(const float4*)(w + h);
        acc += wv.x * sx[h] + wv.y * sx[h + 1] + wv.z * sx[h + 2] + wv.w * sx[h + 3];
    }
    float score = 1.f / (1.f + expf(-acc));
    sscore[tid] = score;
    sbias[tid]  = score + gate_b[tid];
    __syncthreads();

    if (tid == 0) {
        int   idx[TOPK];
        float wts[TOPK];
        float sum = 0.f;
        for (int k = 0; k < TOPK; k++) {
            float best = -1e30f; int bi = 0;
            for (int e = 0; e < E_NUM; e++) {
                float v = sbias[e];
                if (v > best) { best = v; bi = e; }
            }
            sbias[bi] = -1e30f;
            idx[k] = bi;
            wts[k] = sscore[bi];
            sum += wts[k];
        }
        float inv = 1.f / (sum + 1e-20f);
        for (int k = 0; k < TOPK; k++) {
            g_tki[t * TOPK + k] = idx[k];
            g_tkw[t * TOPK + k] = wts[k] * inv;
            atomicAdd(&g_counts[idx[k]], 1);
        }
    }
}

__global__ void zero_counts_kernel() { g_counts[threadIdx.x] = 0; }

__global__ void offsets_kernel() {
    int o = 0;
    for (int e = 0; e < E_NUM; e++) {
        g_offsets[e] = o;
        o += g_counts[e];
        g_cursor[e] = 0;
    }
    g_offsets[E_NUM] = o;
}

__global__ void scatter_kernel() {
    int i = blockIdx.x * blockDim.x + threadIdx.x;
    if (i >= T_TOK * TOPK) return;
    int e = g_tki[i];
    int pos = g_offsets[e] + atomicAdd(&g_cursor[e], 1);
    g_tok[pos]   = i / TOPK;
    g_dest[pos]  = i;
    g_slotw[pos] = g_tkw[i];
}

// ---------------- helpers ----------------
__device__ __forceinline__ uint32_t smem_u32(const void* p) {
    return (uint32_t)__cvta_generic_to_shared(p);
}
__device__ __forceinline__ void cp_async16(uint32_t dst, const void* src, int src_bytes) {
    asm volatile("cp.async.cg.shared.global [%0], [%1], 16, %2;"
                 :: "r"(dst), "l"(src), "r"(src_bytes));
}
#define CP_COMMIT() asm volatile("cp.async.commit_group;" ::: "memory")
#define CP_WAIT2()  asm volatile("cp.async.wait_group 2;" ::: "memory")

__device__ __forceinline__ void ldsm4(uint32_t* r, uint32_t addr) {
    asm volatile("ldmatrix.sync.aligned.m8n8.x4.shared.b16 {%0,%1,%2,%3}, [%4];"
                 : "=r"(r[0]), "=r"(r[1]), "=r"(r[2]), "=r"(r[3]) : "r"(addr));
}
__device__ __forceinline__ void ldsm2t(uint32_t* r, uint32_t addr) {
    asm volatile("ldmatrix.sync.aligned.m8n8.x2.trans.shared.b16 {%0,%1}, [%2];"
                 : "=r"(r[0]), "=r"(r[1]) : "r"(addr));
}
__device__ __forceinline__ void mma16816(float* c, const uint32_t* a, const uint32_t* b) {
    asm volatile(
        "mma.sync.aligned.m16n8k16.row.col.f32.f16.f16.f32 "
        "{%0,%1,%2,%3}, {%4,%5,%6,%7}, {%8,%9}, {%0,%1,%2,%3};"
        : "+f"(c[0]), "+f"(c[1]), "+f"(c[2]), "+f"(c[3])
        : "r"(a[0]), "r"(a[1]), "r"(a[2]), "r"(a[3]), "r"(b[0]), "r"(b[1]));
}

__device__ __forceinline__ void pack_hilo8(const float* f, uint4& hv, uint4& lv) {
    union { uint4 v; __half h[8]; } uh, ul;
    #pragma unroll
    for (int j = 0; j < 8; j++) {
        __half h = __float2half(f[j]);
        uh.h[j] = h;
        ul.h[j] = __float2half(f[j] - __half2float(h));
    }
    hv = uh.v; lv = ul.v;
}
__device__ __forceinline__ uint4 pack_hi8(const float* f) {
    union { uint4 v; __half h[8]; } u;
    #pragma unroll
    for (int j = 0; j < 8; j++) u.h[j] = __float2half(f[j]);
    return u.v;
}

#define ASTRIDE 40  // halfs per A fp16 row (80B, LDSM conflict-free over 8 rows)
#define BSTRIDE 72  // halfs per B fp16 row (144B, LDSM conflict-free over 8 rows)

// smem layouts (dynamic)
struct GUSmem {
    float  A32[3][64 * 32];
    float  B32g[3][32 * 64];
    float  B32u[3][32 * 64];
    __half Ah[64 * ASTRIDE], Al[64 * ASTRIDE];
    __half Bg[32 * BSTRIDE], Bu[32 * BSTRIDE];
};
struct DNSmem {
    float  A32[3][64 * 32];
    float  B32[3][32 * 64];
    __half Ah[64 * ASTRIDE], Al[64 * ASTRIDE];
    __half Bh[32 * BSTRIDE];
};

// ---------------- grouped dual-B GEMM + fused SiLU ----------------
// BM=64, BN=64, BK=32. 256 threads = 8 warps (2M x 4N), warp tile 32x16.
// cp.async 3-stage fp32 staging -> in-smem fp16 conversion -> LDSM/MMA.
template <bool SHARED>
__global__ void __launch_bounds__(256, 2) gateup_kernel(
    const float* __restrict__ x,
    const float* __restrict__ w_gate_all,
    const float* __restrict__ w_up_all) {

    extern __shared__ __align__(16) char smraw[];
    GUSmem& S = *reinterpret_cast<GUSmem*>(smraw);

    const int e = SHARED ? 0 : blockIdx.z;
    int base, nrows;
    if (SHARED) { base = 0; nrows = T_TOK; }
    else        { base = g_offsets[e]; nrows = g_offsets[e + 1] - base; }

    const int m0 = blockIdx.y * 64;
    if (m0 >= nrows) return;
    const int n0 = blockIdx.x * 64;

    const float* wg = SHARED ? w_gate_all : (w_gate_all + (size_t)e * H_DIM * I_DIM);
    const float* wu = SHARED ? w_up_all   : (w_up_all   + (size_t)e * H_DIM * I_DIM);

    const int tid = threadIdx.x;
    // cp.async A mapping: row = tid/4, two float4 at cols (tid%4)*4 and +16
    const int car = tid >> 2;
    const int cac = (tid & 3) * 4;
    const bool avalid = (m0 + car < nrows);
    int tok = 0;
    if (avalid) tok = SHARED ? (m0 + car) : g_tok[base + m0 + car];
    const float* asrc = x + (size_t)tok * H_DIM + cac;
    const int abytes = avalid ? 16 : 0;
    // cp.async B mapping: k-row = tid/8, two float4 at cols (tid%8)*4 and +32
    const int cbr = tid >> 3;
    const int cbc = (tid & 7) * 4;
    const float* gsrc = wg + (size_t)cbr * I_DIM + n0 + cbc;
    const float* usrc = wu + (size_t)cbr * I_DIM + n0 + cbc;

    const int wid  = tid >> 5;
    const int lane = tid & 31;
    const int wm = wid >> 2;   // 0..1
    const int wn = wid & 3;    // 0..3
    const int g  = lane >> 2;
    const int tg = lane & 3;

    float cg[2][2][4] = {};
    float cu[2][2][4] = {};

    const int NIT = H_DIM / 32;

    auto issue = [&](int it) {
        int s = it % 3;
        int k0 = it * 32;
        cp_async16(smem_u32(&S.A32[s][car * 32 + cac]),      asrc + k0,      abytes);
        cp_async16(smem_u32(&S.A32[s][car * 32 + cac + 16]), asrc + k0 + 16, abytes);
        const float* gp = gsrc + (size_t)k0 * I_DIM;
        const float* up = usrc + (size_t)k0 * I_DIM;
        cp_async16(smem_u32(&S.B32g[s][cbr * 64 + cbc]),      gp,      16);
        cp_async16(smem_u32(&S.B32g[s][cbr * 64 + cbc + 32]), gp + 32, 16);
        cp_async16(smem_u32(&S.B32u[s][cbr * 64 + cbc]),      up,      16);
        cp_async16(smem_u32(&S.B32u[s][cbr * 64 + cbc + 32]), up + 32, 16);
        CP_COMMIT();
    };

    issue(0);
    issue(1);

    for (int it = 0; it < NIT; it++) {
        if (it + 2 < NIT) issue(it + 2);
        else              CP_COMMIT();   // keep one group per iteration
        CP_WAIT2();
        __syncthreads();                  // staged fp32 for iter `it` visible; fp16 bufs free

        // convert stage -> fp16 buffers
        const int s = it % 3;
        {
            float f[8];
            #pragma unroll
            for (int j = 0; j < 8; j++) f[j] = S.A32[s][tid * 8 + j];
            uint4 hv, lv;
            pack_hilo8(f, hv, lv);
            int arow = tid >> 2, ac0 = (tid & 3) * 8;
            *(uint4*)&S.Ah[arow * ASTRIDE + ac0] = hv;
            *(uint4*)&S.Al[arow * ASTRIDE + ac0] = lv;

            int brow = tid >> 3, bc0 = (tid & 7) * 8;
            #pragma unroll
            for (int j = 0; j < 8; j++) f[j] = S.B32g[s][tid * 8 + j];
            *(uint4*)&S.Bg[brow * BSTRIDE + bc0] = pack_hi8(f);
            #pragma unroll
            for (int j = 0; j < 8; j++) f[j] = S.B32u[s][tid * 8 + j];
            *(uint4*)&S.Bu[brow * BSTRIDE + bc0] = pack_hi8(f);
        }
        __syncthreads();

        #pragma unroll
        for (int ks = 0; ks < 32; ks += 16) {
            uint32_t ah_f[2][4], al_f[2][4];
            #pragma unroll
            for (int mi = 0; mi < 2; mi++) {
                int row = wm * 32 + mi * 16 + (lane & 15);
                int col = ks + ((lane & 16) >> 1);
                ldsm4(ah_f[mi], smem_u32(&S.Ah[row * ASTRIDE + col]));
                ldsm4(al_f[mi], smem_u32(&S.Al[row * ASTRIDE + col]));
            }
            uint32_t bg_f[2][2], bu_f[2][2];
            #pragma unroll
            for (int ni = 0; ni < 2; ni++) {
                int brow = ks + (lane & 15);
                int bcol = wn * 16 + ni * 8;
                ldsm2t(bg_f[ni], smem_u32(&S.Bg[brow * BSTRIDE + bcol]));
                ldsm2t(bu_f[ni], smem_u32(&S.Bu[brow * BSTRIDE + bcol]));
            }
            #pragma unroll
            for (int mi = 0; mi < 2; mi++) {
                #pragma unroll
                for (int ni = 0; ni < 2; ni++) {
                    mma16816(cg[mi][ni], ah_f[mi], bg_f[ni]);
                    mma16816(cg[mi][ni], al_f[mi], bg_f[ni]);
                    mma16816(cu[mi][ni], ah_f[mi], bu_f[ni]);
                    mma16816(cu[mi][ni], al_f[mi], bu_f[ni]);
                }
            }
        }
    }

    // epilogue: silu(g)*u
    #pragma unroll
    for (int mi = 0; mi < 2; mi++) {
        int r0 = m0 + wm * 32 + mi * 16 + g;
        int r1 = r0 + 8;
        #pragma unroll
        for (int ni = 0; ni < 2; ni++) {
            int c0 = n0 + wn * 16 + ni * 8 + tg * 2;
            if (r0 < nrows) {
                float* orow = SHARED ? (g_sact + (size_t)r0 * I_DIM)
                                     : (g_act  + (size_t)(base + r0) * I_DIM);
                float g0 = cg[mi][ni][0], u0 = cu[mi][ni][0];
                float g1 = cg[mi][ni][1], u1 = cu[mi][ni][1];
                orow[c0]     = (g0 / (1.f + expf(-g0))) * u0;
                orow[c0 + 1] = (g1 / (1.f + expf(-g1))) * u1;
            }
            if (r1 < nrows) {
                float* orow = SHARED ? (g_sact + (size_t)r1 * I_DIM)
                                     : (g_act  + (size_t)(base + r1) * I_DIM);
                float g2 = cg[mi][ni][2], u2 = cu[mi][ni][2];
                float g3 = cg[mi][ni][3], u3 = cu[mi][ni][3];
                orow[c0]     = (g2 / (1.f + expf(-g2))) * u2;
                orow[c0 + 1] = (g3 / (1.f + expf(-g3))) * u3;
            }
        }
    }
}

// ---------------- grouped down-proj GEMM ----------------
// BM=64, BN=64, BK=32. Same pipeline structure.
template <bool SHARED>
__global__ void __launch_bounds__(256, 2) down_kernel(
    const float* __restrict__ w_down_all,
    float* __restrict__ out) {

    extern __shared__ __align__(16) char smraw[];
    DNSmem& S = *reinterpret_cast<DNSmem*>(smraw);

    const int e = SHARED ? 0 : blockIdx.z;
    int base, nrows;
    if (SHARED) { base = 0; nrows = T_TOK; }
    else        { base = g_offsets[e]; nrows = g_offsets[e + 1] - base; }

    const int m0 = blockIdx.y * 64;
    if (m0 >= nrows) return;
    const int n0 = blockIdx.x * 64;

    const float* wd = SHARED ? w_down_all : (w_down_all + (size_t)e * I_DIM * H_DIM);
    const float* Asrc = SHARED ? g_sact : g_act;

    const int tid = threadIdx.x;
    const int car = tid >> 2;
    const int cac = (tid & 3) * 4;
    const bool avalid = (m0 + car < nrows);
    const float* asrc = Asrc + (size_t)(base + (avalid ? (m0 + car) : 0)) * I_DIM + cac;
    const int abytes = avalid ? 16 : 0;

    const int cbr = tid >> 3;
    const int cbc = (tid & 7) * 4;
    const float* bsrc = wd + (size_t)cbr * H_DIM + n0 + cbc;

    const int wid  = tid >> 5;
    const int lane = tid & 31;
    const int wm = wid >> 2;
    const int wn = wid & 3;
    const int g  = lane >> 2;
    const int tg = lane & 3;

    float acc[2][2][4] = {};

    const int NIT = I_DIM / 32;

    auto issue = [&](int it) {
        int s = it % 3;
        int k0 = it * 32;
        cp_async16(smem_u32(&S.A32[s][car * 32 + cac]),      asrc + k0,      abytes);
        cp_async16(smem_u32(&S.A32[s][car * 32 + cac + 16]), asrc + k0 + 16, abytes);
        const float* bp = bsrc + (size_t)k0 * H_DIM;
        cp_async16(smem_u32(&S.B32[s][cbr * 64 + cbc]),      bp,      16);
        cp_async16(smem_u32(&S.B32[s][cbr * 64 + cbc + 32]), bp + 32, 16);
        CP_COMMIT();
    };

    issue(0);
    issue(1);

    for (int it = 0; it < NIT; it++) {
        if (it + 2 < NIT) issue(it + 2);
        else              CP_COMMIT();
        CP_WAIT2();
        __syncthreads();

        const int s = it % 3;
        {
            float f[8];
            #pragma unroll
            for (int j = 0; j < 8; j++) f[j] = S.A32[s][tid * 8 + j];
            uint4 hv, lv;
            pack_hilo8(f, hv, lv);
            int arow = tid >> 2, ac0 = (tid & 3) * 8;
            *(uint4*)&S.Ah[arow * ASTRIDE + ac0] = hv;
            *(uint4*)&S.Al[arow * ASTRIDE + ac0] = lv;

            int brow = tid >> 3, bc0 = (tid & 7) * 8;
            #pragma unroll
            for (int j = 0; j < 8; j++) f[j] = S.B32[s][tid * 8 + j];
            *(uint4*)&S.Bh[brow * BSTRIDE + bc0] = pack_hi8(f);
        }
        __syncthreads();

        #pragma unroll
        for (int ks = 0; ks < 32; ks += 16) {
            uint32_t ah_f[2][4], al_f[2][4];
            #pragma unroll
            for (int mi = 0; mi < 2; mi++) {
                int row = wm * 32 + mi * 16 + (lane & 15);
                int col = ks + ((lane & 16) >> 1);
                ldsm4(ah_f[mi], smem_u32(&S.Ah[row * ASTRIDE + col]));
                ldsm4(al_f[mi], smem_u32(&S.Al[row * ASTRIDE + col]));
            }
            uint32_t b_f[2][2];
            #pragma unroll
            for (int ni = 0; ni < 2; ni++) {
                int brow = ks + (lane & 15);
                int bcol = wn * 16 + ni * 8;
                ldsm2t(b_f[ni], smem_u32(&S.Bh[brow * BSTRIDE + bcol]));
            }
            #pragma unroll
            for (int mi = 0; mi < 2; mi++) {
                #pragma unroll
                for (int ni = 0; ni < 2; ni++) {
                    mma16816(acc[mi][ni], ah_f[mi], b_f[ni]);
                    mma16816(acc[mi][ni], al_f[mi], b_f[ni]);
                }
            }
        }
    }

    #pragma unroll
    for (int mi = 0; mi < 2; mi++) {
        int rr[2] = {m0 + wm * 32 + mi * 16 + g, m0 + wm * 32 + mi * 16 + g + 8};
        #pragma unroll
        for (int half = 0; half < 2; half++) {
            int r = rr[half];
            if (r >= nrows) continue;
            #pragma unroll
            for (int ni = 0; ni < 2; ni++) {
                int c0 = n0 + wn * 16 + ni * 8 + tg * 2;
                float v0 = acc[mi][ni][half * 2 + 0];
                float v1 = acc[mi][ni][half * 2 + 1];
                if (SHARED) {
                    float* orow = out + (size_t)r * H_DIM;
                    orow[c0]     = v0;
                    orow[c0 + 1] = v1;
                } else {
                    int slot = base + r;
                    int dest = g_dest[slot];
                    float w  = g_slotw[slot];
                    float* orow = g_partial + (size_t)dest * H_DIM;
                    orow[c0]     = w * v0;
                    orow[c0 + 1] = w * v1;
                }
            }
        }
    }
}

// ---------------- combine ----------------
__global__ void combine_kernel(float* __restrict__ out) {
    int i = blockIdx.x * blockDim.x + threadIdx.x;
    int t = i / H_DIM;
    int h = i - t * H_DIM;
    float acc = out[i];
    #pragma unroll
    for (int k = 0; k < TOPK; k++)
        acc += g_partial[((size_t)t * TOPK + k) * H_DIM + h];
    out[i] = acc;
}

// ---------------- launch ----------------
extern "C" void kernel_launch(void* const* d_in, const int* in_sizes, int n_in,
                              void* d_out, int out_size) {
    const float* x       = (const float*)d_in[0];
    const float* gate_w  = (const float*)d_in[1];
    const float* gate_b  = (const float*)d_in[2];
    const float* w_gate  = (const float*)d_in[3];
    const float* w_up    = (const float*)d_in[4];
    const float* w_down  = (const float*)d_in[5];
    const float* sw_gate = (const float*)d_in[6];
    const float* sw_up   = (const float*)d_in[7];
    const float* sw_down = (const float*)d_in[8];
    float* out = (float*)d_out;

    const int GU_SMEM = (int)sizeof(GUSmem);  // ~93 KB
    const int DN_SMEM = (int)sizeof(DNSmem);  // ~64 KB
    cudaFuncSetAttribute(gateup_kernel<false>, cudaFuncAttributeMaxDynamicSharedMemorySize, GU_SMEM);
    cudaFuncSetAttribute(gateup_kernel<true>,  cudaFuncAttributeMaxDynamicSharedMemorySize, GU_SMEM);
    cudaFuncSetAttribute(down_kernel<false>,   cudaFuncAttributeMaxDynamicSharedMemorySize, DN_SMEM);
    cudaFuncSetAttribute(down_kernel<true>,    cudaFuncAttributeMaxDynamicSharedMemorySize, DN_SMEM);

    // Order chosen so the ncu fixed-slot capture lands on a GEMM (down<true>),
    // not a tiny setup kernel. Shared-expert path is router-independent.
    zero_counts_kernel<<<1, 64>>>();
    gateup_kernel<true><<<dim3(I_DIM / 64, T_TOK / 64, 1), 256, GU_SMEM>>>(x, sw_gate, sw_up);
    router_kernel<<<T_TOK, 64>>>(x, gate_w, gate_b);
    down_kernel<true><<<dim3(H_DIM / 64, T_TOK / 64, 1), 256, DN_SMEM>>>(sw_down, out);
    offsets_kernel<<<1, 1>>>();
    scatter_kernel<<<(T_TOK * TOPK + 255) / 256, 256>>>();
    gateup_kernel<false><<<dim3(I_DIM / 64, 8, E_NUM), 256, GU_SMEM>>>(x, w_gate, w_up);
    down_kernel<false><<<dim3(H_DIM / 64, 8, E_NUM), 256, DN_SMEM>>>(w_down, nullptr);
    combine_kernel<<<(T_TOK * H_DIM) / 256, 256>>>(out);
}